// round 2
// baseline (speedup 1.0000x reference)
#include <cuda_runtime.h>

// Problem constants
#define NCH     3
#define HH      4096
#define WW      4096
#define NHB     512          // blocks per column (H/8)
#define NWB     512          // blocks per row (W/8)
#define KCO     16           // kept coeffs per 8x8 block
#define PPB     8192         // params per strip = NWB*KCO
#define NSTRIP  1536         // NCH*NHB
#define NTHR    256
#define NTOT    12582912ll   // total params
#define SSTRIDE 17           // padded shared stride per block (kills bank conflicts)

// Per-strip partial sums: .x = sum(eps^2), .y = sum(log_std)
__device__ double2 g_part[NSTRIP];
__device__ unsigned int g_count = 0;   // arrival counter (reset each run by last CTA)

// Inverse zig-zag: for (u,v) in 8x8 block, which of the first-16 zigzag coeffs
// lands there (-1 = dropped).
__constant__ signed char c_inv[64] = {
     0,  2,  3,  9, 10, -1, -1, -1,
     1,  4,  8, 11, -1, -1, -1, -1,
     5,  7, 12, -1, -1, -1, -1, -1,
     6, 13, -1, -1, -1, -1, -1, -1,
    14, -1, -1, -1, -1, -1, -1, -1,
    15, -1, -1, -1, -1, -1, -1, -1,
    -1, -1, -1, -1, -1, -1, -1, -1,
    -1, -1, -1, -1, -1, -1, -1, -1
};

__global__ __launch_bounds__(NTHR, 1)
void dct_main(const float* __restrict__ mean,
              const float* __restrict__ log_std,
              const float* __restrict__ eps,
              float* __restrict__ out,
              long long scal_off)
{
    __shared__ float s_samp[NWB * SSTRIDE];   // 512 blocks * 17 floats = 34816 B
    __shared__ float s_r1[8], s_r2[8];
    __shared__ signed char s_inv[64];
    __shared__ bool s_last;
    __shared__ double s_d1[8], s_d2[8];

    const int tid = threadIdx.x;
    const int cb  = blockIdx.x;               // c*NHB + bh
    const long long base = (long long)cb * PPB;

    if (tid < 64) s_inv[tid] = c_inv[tid];

    // ---- Phase 1: compute samples into shared, accumulate reductions ----
    const float4* m4 = (const float4*)(mean    + base);
    const float4* l4 = (const float4*)(log_std + base);
    const float4* e4 = (const float4*)(eps     + base);

    float a1 = 0.f, a2 = 0.f;
    #pragma unroll
    for (int it = 0; it < PPB / 4 / NTHR; ++it) {   // 8 iters
        int i = tid + it * NTHR;                    // float4 index within strip
        float4 m  = __ldcs(m4 + i);
        float4 ls = __ldcs(l4 + i);
        float4 e  = __ldcs(e4 + i);

        int j   = i << 2;                 // element index (multiple of 4)
        int blk = j >> 4;                 // bw block
        int off = j & 15;                 // 0,4,8,12 -> stays inside one block
        float* dst = &s_samp[blk * SSTRIDE + off];
        dst[0] = fmaf(__expf(ls.x), e.x, m.x);
        dst[1] = fmaf(__expf(ls.y), e.y, m.y);
        dst[2] = fmaf(__expf(ls.z), e.z, m.z);
        dst[3] = fmaf(__expf(ls.w), e.w, m.w);

        a1 = fmaf(e.x, e.x, a1); a1 = fmaf(e.y, e.y, a1);
        a1 = fmaf(e.z, e.z, a1); a1 = fmaf(e.w, e.w, a1);
        a2 += (ls.x + ls.y) + (ls.z + ls.w);
    }

    // warp reduce
    #pragma unroll
    for (int o = 16; o; o >>= 1) {
        a1 += __shfl_down_sync(0xffffffffu, a1, o);
        a2 += __shfl_down_sync(0xffffffffu, a2, o);
    }
    if ((tid & 31) == 0) { s_r1[tid >> 5] = a1; s_r2[tid >> 5] = a2; }

    __syncthreads();   // also publishes s_samp + s_inv for phase 2

    if (tid == 0) {
        double d1 = 0.0, d2 = 0.0;
        #pragma unroll
        for (int w = 0; w < 8; ++w) { d1 += (double)s_r1[w]; d2 += (double)s_r2[w]; }
        g_part[cb] = make_double2(d1, d2);
    }

    // ---- Phase 2: dense write of the 8 x 4096 strip (float4, coalesced) ----
    float4* out4 = (float4*)(out + (long long)cb * (8ll * WW));
    #pragma unroll
    for (int it = 0; it < (8 * WW / 4) / NTHR; ++it) {   // 32 iters
        int i  = tid + it * NTHR;          // float4 index in strip (0..8191)
        int u  = i >> 10;                  // row within block (0..7)
        int xq = i & 1023;                 // float4 index within row
        int bw = xq >> 1;                  // block column
        int v0 = (xq & 1) << 2;            // 0 or 4
        const signed char* inv = &s_inv[(u << 3) + v0];
        const float* sp = &s_samp[bw * SSTRIDE];

        float4 val = make_float4(0.f, 0.f, 0.f, 0.f);
        int k;
        k = inv[0]; if (k >= 0) val.x = sp[k];
        k = inv[1]; if (k >= 0) val.y = sp[k];
        k = inv[2]; if (k >= 0) val.z = sp[k];
        k = inv[3]; if (k >= 0) val.w = sp[k];
        __stcs(out4 + i, val);
    }

    // ---- Phase 3: last CTA to arrive performs the global finalize ----
    __threadfence();                       // publish g_part[cb] + out stores
    if (tid == 0) {
        unsigned int prev = atomicAdd(&g_count, 1u);
        s_last = (prev == NSTRIP - 1);
    }
    __syncthreads();

    if (s_last) {
        double d1 = 0.0, d2 = 0.0;
        for (int i = tid; i < NSTRIP; i += NTHR) {   // 6 per thread, fixed order
            double2 p = g_part[i];
            d1 += p.x; d2 += p.y;
        }
        #pragma unroll
        for (int o = 16; o; o >>= 1) {
            d1 += __shfl_down_sync(0xffffffffu, d1, o);
            d2 += __shfl_down_sync(0xffffffffu, d2, o);
        }
        if ((tid & 31) == 0) { s_d1[tid >> 5] = d1; s_d2[tid >> 5] = d2; }
        __syncthreads();
        if (tid == 0) {
            double S1 = 0.0, S2 = 0.0;
            #pragma unroll
            for (int w = 0; w < 8; ++w) { S1 += s_d1[w]; S2 += s_d2[w]; }
            const double LOG2PI = 1.8378770664093454836;
            double log_prob = -0.5 * (S1 + 2.0 * S2 + (double)NTOT * LOG2PI);
            double entropy  = (double)NTOT * 0.5 * (1.0 + LOG2PI) + S2;
            out[scal_off]     = (float)log_prob;
            out[scal_off + 1] = (float)entropy;
            g_count = 0;                   // reset for next graph replay
        }
    }
}

extern "C" void kernel_launch(void* const* d_in, const int* in_sizes, int n_in,
                              void* d_out, int out_size)
{
    const float* mean    = (const float*)d_in[0];
    const float* log_std = (const float*)d_in[1];
    const float* eps     = (const float*)d_in[2];
    // d_in[3] (flat_idx) intentionally unused: the index pattern is static and
    // recomputed on the fly -> saves 50 MB of HBM reads.
    float* out = (float*)d_out;

    dct_main<<<NSTRIP, NTHR>>>(mean, log_std, eps, out,
                               (long long)out_size - 2);
}

// round 3
// speedup vs baseline: 1.2091x; 1.2091x over previous
#include <cuda_runtime.h>

// Problem constants
#define NCH     3
#define HH      4096
#define WW      4096
#define NHB     512          // blocks per column (H/8)
#define NWB     512          // blocks per row (W/8)
#define KCO     16           // kept coeffs per 8x8 block
#define PPB     8192         // params per strip = NWB*KCO
#define NSTRIP  1536         // NCH*NHB
#define NTHR    256
#define NTOT    12582912ll   // total params
#define SSTRIDE 17           // padded shared stride per block (kills bank conflicts)

// Per-strip partial sums: .x = sum(eps^2), .y = sum(log_std)
__device__ double2 g_part[NSTRIP];
__device__ unsigned int g_count = 0;   // arrival counter (reset each run by last CTA)

// Inverse zig-zag: for (u,v) in 8x8 block, which of the first-16 zigzag coeffs
// lands there (-1 = dropped).
__constant__ signed char c_inv[64] = {
     0,  2,  3,  9, 10, -1, -1, -1,
     1,  4,  8, 11, -1, -1, -1, -1,
     5,  7, 12, -1, -1, -1, -1, -1,
     6, 13, -1, -1, -1, -1, -1, -1,
    14, -1, -1, -1, -1, -1, -1, -1,
    15, -1, -1, -1, -1, -1, -1, -1,
    -1, -1, -1, -1, -1, -1, -1, -1,
    -1, -1, -1, -1, -1, -1, -1, -1
};

__global__ __launch_bounds__(NTHR, 4)   // cap regs at 64 -> 4 CTAs/SM
void dct_main(const float* __restrict__ mean,
              const float* __restrict__ log_std,
              const float* __restrict__ eps,
              float* __restrict__ out,
              long long scal_off)
{
    __shared__ float s_samp[NWB * SSTRIDE];   // 512 blocks * 17 floats = 34816 B
    __shared__ float s_r1[8], s_r2[8];
    __shared__ signed char s_inv[64];
    __shared__ bool s_last;
    __shared__ double s_d1[8], s_d2[8];

    const int tid = threadIdx.x;
    const int cb  = blockIdx.x;               // c*NHB + bh
    const long long base = (long long)cb * PPB;

    if (tid < 64) s_inv[tid] = c_inv[tid];

    // ---- Phase 1: compute samples into shared, accumulate reductions ----
    const float4* m4 = (const float4*)(mean    + base);
    const float4* l4 = (const float4*)(log_std + base);
    const float4* e4 = (const float4*)(eps     + base);

    float a1 = 0.f, a2 = 0.f;
    #pragma unroll 2
    for (int it = 0; it < PPB / 4 / NTHR; ++it) {   // 8 iters
        int i = tid + it * NTHR;                    // float4 index within strip
        float4 m  = m4[i];
        float4 ls = l4[i];
        float4 e  = e4[i];

        int j   = i << 2;                 // element index (multiple of 4)
        int blk = j >> 4;                 // bw block
        int off = j & 15;                 // 0,4,8,12 -> stays inside one block
        float* dst = &s_samp[blk * SSTRIDE + off];
        dst[0] = fmaf(__expf(ls.x), e.x, m.x);
        dst[1] = fmaf(__expf(ls.y), e.y, m.y);
        dst[2] = fmaf(__expf(ls.z), e.z, m.z);
        dst[3] = fmaf(__expf(ls.w), e.w, m.w);

        a1 = fmaf(e.x, e.x, a1); a1 = fmaf(e.y, e.y, a1);
        a1 = fmaf(e.z, e.z, a1); a1 = fmaf(e.w, e.w, a1);
        a2 += (ls.x + ls.y) + (ls.z + ls.w);
    }

    // warp reduce
    #pragma unroll
    for (int o = 16; o; o >>= 1) {
        a1 += __shfl_down_sync(0xffffffffu, a1, o);
        a2 += __shfl_down_sync(0xffffffffu, a2, o);
    }
    if ((tid & 31) == 0) { s_r1[tid >> 5] = a1; s_r2[tid >> 5] = a2; }

    __syncthreads();   // also publishes s_samp + s_inv for phase 2

    if (tid == 0) {
        double d1 = 0.0, d2 = 0.0;
        #pragma unroll
        for (int w = 0; w < 8; ++w) { d1 += (double)s_r1[w]; d2 += (double)s_r2[w]; }
        g_part[cb] = make_double2(d1, d2);
    }

    // ---- Phase 2: dense write of the 8 x 4096 strip (float4, coalesced) ----
    float4* out4 = (float4*)(out + (long long)cb * (8ll * WW));
    #pragma unroll 4
    for (int it = 0; it < (8 * WW / 4) / NTHR; ++it) {   // 32 iters
        int i  = tid + it * NTHR;          // float4 index in strip (0..8191)
        int u  = i >> 10;                  // row within block (0..7)
        int xq = i & 1023;                 // float4 index within row
        int bw = xq >> 1;                  // block column
        int v0 = (xq & 1) << 2;            // 0 or 4
        const signed char* inv = &s_inv[(u << 3) + v0];
        const float* sp = &s_samp[bw * SSTRIDE];

        float4 val = make_float4(0.f, 0.f, 0.f, 0.f);
        int k;
        k = inv[0]; if (k >= 0) val.x = sp[k];
        k = inv[1]; if (k >= 0) val.y = sp[k];
        k = inv[2]; if (k >= 0) val.z = sp[k];
        k = inv[3]; if (k >= 0) val.w = sp[k];
        out4[i] = val;
    }

    // ---- Phase 3: last CTA to arrive performs the global finalize ----
    __threadfence();                       // publish g_part[cb] + out stores
    if (tid == 0) {
        unsigned int prev = atomicAdd(&g_count, 1u);
        s_last = (prev == NSTRIP - 1);
    }
    __syncthreads();

    if (s_last) {
        double d1 = 0.0, d2 = 0.0;
        for (int i = tid; i < NSTRIP; i += NTHR) {   // 6 per thread, fixed order
            double2 p = g_part[i];
            d1 += p.x; d2 += p.y;
        }
        #pragma unroll
        for (int o = 16; o; o >>= 1) {
            d1 += __shfl_down_sync(0xffffffffu, d1, o);
            d2 += __shfl_down_sync(0xffffffffu, d2, o);
        }
        if ((tid & 31) == 0) { s_d1[tid >> 5] = d1; s_d2[tid >> 5] = d2; }
        __syncthreads();
        if (tid == 0) {
            double S1 = 0.0, S2 = 0.0;
            #pragma unroll
            for (int w = 0; w < 8; ++w) { S1 += s_d1[w]; S2 += s_d2[w]; }
            const double LOG2PI = 1.8378770664093454836;
            double log_prob = -0.5 * (S1 + 2.0 * S2 + (double)NTOT * LOG2PI);
            double entropy  = (double)NTOT * 0.5 * (1.0 + LOG2PI) + S2;
            out[scal_off]     = (float)log_prob;
            out[scal_off + 1] = (float)entropy;
            g_count = 0;                   // reset for next graph replay
        }
    }
}

extern "C" void kernel_launch(void* const* d_in, const int* in_sizes, int n_in,
                              void* d_out, int out_size)
{
    const float* mean    = (const float*)d_in[0];
    const float* log_std = (const float*)d_in[1];
    const float* eps     = (const float*)d_in[2];
    // d_in[3] (flat_idx) intentionally unused: the index pattern is static and
    // recomputed on the fly -> saves 50 MB of HBM reads.
    float* out = (float*)d_out;

    dct_main<<<NSTRIP, NTHR>>>(mean, log_std, eps, out,
                               (long long)out_size - 2);
}